// round 4
// baseline (speedup 1.0000x reference)
#include <cuda_runtime.h>
#include <cstdint>

// ===========================================================================
// WireframeDiscriminator: render -> conv1..3 (5x5 s2 + BN(batch) + LReLU)
//                         -> conv4 (8x8 dense == GEMM) + BN + LReLU -> conv5
// All fp32. All scratch in __device__ globals (no allocation). Deterministic.
// ===========================================================================

#define NB 64   // batch

// ---------------- scratch ----------------
__device__ __align__(16) float g_rend[NB*14*64*64];    // 14.7 MB
__device__ __align__(16) float g_h1[NB*64*32*32];      // 16.8 MB
__device__ __align__(16) float g_h2[NB*128*16*16];     //  8.4 MB
__device__ __align__(16) float g_h3[NB*256*8*8];       //  4.2 MB
__device__ __align__(16) float g_h4[NB*1024];
__device__ __align__(16) float g_h4p[16*NB*1024];      // split-K partials
__device__ __align__(16) float g_w1t[14*25*64];
__device__ __align__(16) float g_w2t[64*25*128];
__device__ __align__(16) float g_w3t[128*25*256];
__device__ float g_scale[1024];
__device__ float g_shift[1024];

// ---------------- weight transpose: [oc][ic][kh][kw] -> [ic][kh][kw][oc] ----
template<int OC,int IC,int KS>
__global__ void wtrans_kernel(const float* __restrict__ w, float* __restrict__ wt){
    int n = OC*IC*KS*KS;
    int i = blockIdx.x*blockDim.x + threadIdx.x;
    if (i >= n) return;
    int kw = i % KS; int t = i / KS;
    int kh = t % KS; t /= KS;
    int ic = t % IC; int oc = t / IC;
    wt[((ic*KS + kh)*KS + kw)*OC + oc] = w[i];
}

// ---------------- render: elements (B,46,18) -> g_rend (B,14,64,64) --------
__global__ void render_kernel(const float* __restrict__ elems){
    __shared__ float s_cls[46][14];
    __shared__ float s_rect[46][4];
    __shared__ float s_geo[46][4];   // x0,x1,y0,y1
    int b   = blockIdx.x >> 4;
    int pix = ((blockIdx.x & 15) << 8) + threadIdx.x;   // 0..4095
    const float* eb = elems + b*46*18;
    for (int i = threadIdx.x; i < 46*18; i += 256){
        int n = i/18, c = i%18;
        float v = eb[i];
        if (c < 14) s_cls[n][c] = v; else s_rect[n][c-14] = v;
    }
    __syncthreads();
    if (threadIdx.x < 46){
        int n = threadIdx.x;
        float x = s_rect[n][0]*64.f, y = s_rect[n][1]*64.f;
        float w = s_rect[n][2]*64.f, h = s_rect[n][3]*64.f;
        s_geo[n][0] = x - 0.5f*w;
        s_geo[n][1] = x + 0.5f*w;
        s_geo[n][2] = y - 0.5f*h;
        s_geo[n][3] = y + 0.5f*h;
    }
    __syncthreads();

    float cy = (float)(pix >> 6);
    float cx = (float)(pix & 63);
    float acc[14];
    #pragma unroll
    for (int c = 0; c < 14; c++) acc[c] = 0.f;

    for (int n = 0; n < 46; n++){
        float x0 = s_geo[n][0], x1 = s_geo[n][1];
        float y0 = s_geo[n][2], y1 = s_geo[n][3];
        float by = __saturatef(cy - y0) * __saturatef(y1 - cy);
        float bx = __saturatef(cx - x0) * __saturatef(x1 - cx);
        float l0 = fmaxf(1.f - fabsf(cx - x0), 0.f) * by;
        float l1 = fmaxf(1.f - fabsf(cx - x1), 0.f) * by;
        float l2 = fmaxf(1.f - fabsf(cy - y0), 0.f) * bx;
        float l3 = fmaxf(1.f - fabsf(cy - y1), 0.f) * bx;
        float r  = fmaxf(fmaxf(l0, l1), fmaxf(l2, l3));
        if (r > 0.f){
            #pragma unroll
            for (int c = 0; c < 14; c++) acc[c] = fmaf(s_cls[n][c], r, acc[c]);
        }
    }
    float* ob = g_rend + (size_t)b*14*4096 + pix;
    #pragma unroll
    for (int c = 0; c < 14; c++) ob[c*4096] = acc[c];
}

// ---------------- direct 5x5 stride-2 pad-2 conv, 4oc x 4ow register tile --
// weights pre-transposed to [ic][kh][kw][oc]; block = (b, oh); 128 threads.
template<int IC,int IH,int IW,int OC,int OH,int OW>
__global__ void __launch_bounds__(128)
conv5s2_kernel(const float* __restrict__ in, const float* __restrict__ wt,
               float* __restrict__ out){
    constexpr int KS = 5, ST = 2, PD = 2, OCT = 4, OWT = 4;
    constexpr int NOWT = OW/OWT;
    constexpr int SPAN = (OWT-1)*ST + KS;   // 11
    int tid   = threadIdx.x;
    int owt   = tid % NOWT;
    int oct   = tid / NOWT;
    int b     = blockIdx.x / OH;
    int oh    = blockIdx.x % OH;
    int ow0   = owt*OWT;
    int xbase = ow0*ST - PD;
    int ybase = oh*ST - PD;

    float acc[OWT][OCT];
    #pragma unroll
    for (int i = 0; i < OWT; i++)
        #pragma unroll
        for (int j = 0; j < OCT; j++) acc[i][j] = 0.f;

    const float* ip0 = in + (size_t)b*IC*IH*IW;
    #pragma unroll 1
    for (int ic = 0; ic < IC; ++ic){
        const float* ip = ip0 + ic*IH*IW;
        const float* wp = wt + ic*KS*KS*OC + oct*OCT;
        #pragma unroll
        for (int kh = 0; kh < KS; ++kh){
            int y = ybase + kh;
            float v[SPAN];
            if ((unsigned)y < (unsigned)IH){
                const float* row = ip + y*IW;
                #pragma unroll
                for (int s = 0; s < SPAN; s++){
                    int x = xbase + s;
                    v[s] = ((unsigned)x < (unsigned)IW) ? __ldg(row + x) : 0.f;
                }
            } else {
                #pragma unroll
                for (int s = 0; s < SPAN; s++) v[s] = 0.f;
            }
            #pragma unroll
            for (int kw = 0; kw < KS; ++kw){
                float4 wv = *reinterpret_cast<const float4*>(wp + (kh*KS + kw)*OC);
                #pragma unroll
                for (int i = 0; i < OWT; i++){
                    float xv = v[kw + i*ST];
                    acc[i][0] = fmaf(xv, wv.x, acc[i][0]);
                    acc[i][1] = fmaf(xv, wv.y, acc[i][1]);
                    acc[i][2] = fmaf(xv, wv.z, acc[i][2]);
                    acc[i][3] = fmaf(xv, wv.w, acc[i][3]);
                }
            }
        }
    }
    #pragma unroll
    for (int j = 0; j < OCT; j++){
        float* op = out + (((size_t)b*OC + oct*OCT + j)*OH + oh)*OW + ow0;
        #pragma unroll
        for (int i = 0; i < OWT; i++) op[i] = acc[i][j];
    }
}

// ---------------- BN (batch statistics over N,H,W) --------------------------
template<int C,int HW>
__global__ void bn_stats_kernel(const float* __restrict__ x,
                                const float* __restrict__ gamma,
                                const float* __restrict__ beta){
    int c = blockIdx.x;
    double s = 0.0, ss = 0.0;
    for (int b = 0; b < NB; b++){
        const float* p = x + ((size_t)b*C + c)*HW;
        for (int i = threadIdx.x; i < HW; i += blockDim.x){
            float v = p[i];
            s  += v;
            ss += (double)v * (double)v;
        }
    }
    __shared__ double sh_s[256], sh_ss[256];
    int tid = threadIdx.x;
    sh_s[tid] = s; sh_ss[tid] = ss;
    __syncthreads();
    for (int st = 128; st > 0; st >>= 1){
        if (tid < st){ sh_s[tid] += sh_s[tid+st]; sh_ss[tid] += sh_ss[tid+st]; }
        __syncthreads();
    }
    if (tid == 0){
        double n   = (double)NB * (double)HW;
        double m   = sh_s[0] / n;
        double var = sh_ss[0] / n - m*m;
        float rstd = (float)rsqrt(var + 1e-5);
        float g    = gamma[c];
        g_scale[c] = g * rstd;
        g_shift[c] = beta[c] - (float)m * g * rstd;
    }
}

template<int C,int HW>
__global__ void bn_apply_kernel(float* __restrict__ x){
    int i = blockIdx.x*blockDim.x + threadIdx.x;    // grid sized exactly
    int c = (i / HW) % C;
    float v = fmaf(x[i], g_scale[c], g_shift[c]);
    x[i] = (v >= 0.f) ? v : 0.01f*v;
}

// ---------------- conv4 as split-K GEMM: [64 x 16384] x [16384 x 1024] -----
// grid = 16 oc-blocks * 16 K-splits; block tile 64b x 64oc; thread 4x4.
__global__ void __launch_bounds__(256)
gemm_kernel(const float* __restrict__ W4){
    constexpr int KC = 16;
    constexpr int KSPLIT = 16;
    constexpr int KLEN = 16384 / KSPLIT;   // 1024
    int ocb = blockIdx.x / KSPLIT;
    int ks  = blockIdx.x % KSPLIT;
    int tid = threadIdx.x;
    int tx  = tid & 15;        // -> 4 oc
    int ty  = tid >> 4;        // -> 4 b
    __shared__ __align__(16) float As[KC][68];
    __shared__ __align__(16) float Ws[KC][68];

    float acc[4][4];
    #pragma unroll
    for (int i = 0; i < 4; i++)
        #pragma unroll
        for (int j = 0; j < 4; j++) acc[i][j] = 0.f;

    const float* A  = g_h3;
    const float* Wb = W4 + (size_t)ocb*64*16384;
    int k0 = ks*KLEN;

    for (int kc = 0; kc < KLEN; kc += KC){
        #pragma unroll
        for (int l = 0; l < 4; l++){
            int idx = tid + l*256;
            int r = idx >> 4, kk = idx & 15;
            As[kk][r] = A [(size_t)r*16384 + k0 + kc + kk];
            Ws[kk][r] = Wb[(size_t)r*16384 + k0 + kc + kk];
        }
        __syncthreads();
        #pragma unroll
        for (int kk = 0; kk < KC; kk++){
            float4 a = *reinterpret_cast<const float4*>(&As[kk][ty*4]);
            float4 w = *reinterpret_cast<const float4*>(&Ws[kk][tx*4]);
            acc[0][0]=fmaf(a.x,w.x,acc[0][0]); acc[0][1]=fmaf(a.x,w.y,acc[0][1]);
            acc[0][2]=fmaf(a.x,w.z,acc[0][2]); acc[0][3]=fmaf(a.x,w.w,acc[0][3]);
            acc[1][0]=fmaf(a.y,w.x,acc[1][0]); acc[1][1]=fmaf(a.y,w.y,acc[1][1]);
            acc[1][2]=fmaf(a.y,w.z,acc[1][2]); acc[1][3]=fmaf(a.y,w.w,acc[1][3]);
            acc[2][0]=fmaf(a.z,w.x,acc[2][0]); acc[2][1]=fmaf(a.z,w.y,acc[2][1]);
            acc[2][2]=fmaf(a.z,w.z,acc[2][2]); acc[2][3]=fmaf(a.z,w.w,acc[2][3]);
            acc[3][0]=fmaf(a.w,w.x,acc[3][0]); acc[3][1]=fmaf(a.w,w.y,acc[3][1]);
            acc[3][2]=fmaf(a.w,w.z,acc[3][2]); acc[3][3]=fmaf(a.w,w.w,acc[3][3]);
        }
        __syncthreads();
    }
    float* op = g_h4p + (size_t)ks*NB*1024;
    #pragma unroll
    for (int i = 0; i < 4; i++)
        #pragma unroll
        for (int j = 0; j < 4; j++)
            op[(ty*4 + i)*1024 + ocb*64 + tx*4 + j] = acc[i][j];
}

// deterministic split-K reduction
__global__ void ksum_kernel(){
    int i = blockIdx.x*blockDim.x + threadIdx.x;   // 65536 threads
    float s = 0.f;
    #pragma unroll
    for (int k = 0; k < 16; k++) s += g_h4p[(size_t)k*NB*1024 + i];
    g_h4[i] = s;
}

// ---------------- BN4 (per channel over 64 batch values) -------------------
__global__ void bn4_stats_kernel(const float* __restrict__ gamma,
                                 const float* __restrict__ beta){
    int c = blockIdx.x*blockDim.x + threadIdx.x;   // 1024 threads
    float s = 0.f, ss = 0.f;
    for (int b = 0; b < NB; b++){
        float v = g_h4[b*1024 + c];
        s += v; ss += v*v;
    }
    float m    = s * (1.f/NB);
    float var  = ss * (1.f/NB) - m*m;
    float rstd = rsqrtf(var + 1e-5f);
    float g    = gamma[c];
    g_scale[c] = g * rstd;
    g_shift[c] = beta[c] - m * g * rstd;
}

// ---------------- final: lrelu(bn4(h4)) . w5 + b5 --------------------------
__global__ void final_kernel(const float* __restrict__ w5,
                             const float* __restrict__ b5,
                             float* __restrict__ out){
    int b = blockIdx.x, tid = threadIdx.x;
    float p = 0.f;
    for (int c = tid; c < 1024; c += 128){
        float v = fmaf(g_h4[b*1024 + c], g_scale[c], g_shift[c]);
        v = (v >= 0.f) ? v : 0.01f*v;
        p = fmaf(w5[c], v, p);
    }
    __shared__ float red[128];
    red[tid] = p;
    __syncthreads();
    for (int st = 64; st > 0; st >>= 1){
        if (tid < st) red[tid] += red[tid + st];
        __syncthreads();
    }
    if (tid == 0) out[b] = red[0] + b5[0];
}

// ===========================================================================
extern "C" void kernel_launch(void* const* d_in, const int* in_sizes, int n_in,
                              void* d_out, int out_size){
    const float* input_data = (const float*)d_in[0];
    // d_in[1] = input_length (unused by reference)
    const float* w1 = (const float*)d_in[2];
    const float* g1 = (const float*)d_in[3];
    const float* b1 = (const float*)d_in[4];
    const float* w2 = (const float*)d_in[5];
    const float* g2 = (const float*)d_in[6];
    const float* b2 = (const float*)d_in[7];
    const float* w3 = (const float*)d_in[8];
    const float* g3 = (const float*)d_in[9];
    const float* b3 = (const float*)d_in[10];
    const float* w4 = (const float*)d_in[11];
    const float* g4 = (const float*)d_in[12];
    const float* b4 = (const float*)d_in[13];
    const float* w5 = (const float*)d_in[14];
    const float* b5 = (const float*)d_in[15];
    float* out = (float*)d_out;

    float *p_rend, *p_h1, *p_h2, *p_h3, *p_w1t, *p_w2t, *p_w3t;
    cudaGetSymbolAddress((void**)&p_rend, g_rend);
    cudaGetSymbolAddress((void**)&p_h1,   g_h1);
    cudaGetSymbolAddress((void**)&p_h2,   g_h2);
    cudaGetSymbolAddress((void**)&p_h3,   g_h3);
    cudaGetSymbolAddress((void**)&p_w1t,  g_w1t);
    cudaGetSymbolAddress((void**)&p_w2t,  g_w2t);
    cudaGetSymbolAddress((void**)&p_w3t,  g_w3t);

    // weight transposes (tiny)
    wtrans_kernel<64,14,5>  <<<(64*14*25   + 255)/256, 256>>>(w1, p_w1t);
    wtrans_kernel<128,64,5> <<<(128*64*25  + 255)/256, 256>>>(w2, p_w2t);
    wtrans_kernel<256,128,5><<<(256*128*25 + 255)/256, 256>>>(w3, p_w3t);

    // render
    render_kernel<<<NB*16, 256>>>(input_data);

    // conv1 + BN + LReLU
    conv5s2_kernel<14,64,64, 64,32,32><<<NB*32, 128>>>(p_rend, p_w1t, p_h1);
    bn_stats_kernel<64,1024><<<64, 256>>>(p_h1, g1, b1);
    bn_apply_kernel<64,1024><<<(NB*64*1024)/256, 256>>>(p_h1);

    // conv2 + BN + LReLU
    conv5s2_kernel<64,32,32, 128,16,16><<<NB*16, 128>>>(p_h1, p_w2t, p_h2);
    bn_stats_kernel<128,256><<<128, 256>>>(p_h2, g2, b2);
    bn_apply_kernel<128,256><<<(NB*128*256)/256, 256>>>(p_h2);

    // conv3 + BN + LReLU
    conv5s2_kernel<128,16,16, 256,8,8><<<NB*8, 128>>>(p_h2, p_w3t, p_h3);
    bn_stats_kernel<256,64><<<256, 256>>>(p_h3, g3, b3);
    bn_apply_kernel<256,64><<<(NB*256*64)/256, 256>>>(p_h3);

    // conv4 (split-K GEMM, deterministic reduce) + BN4
    gemm_kernel<<<16*16, 256>>>(w4);
    ksum_kernel<<<(NB*1024)/256, 256>>>();
    bn4_stats_kernel<<<4, 256>>>(g4, b4);

    // conv5 + bias -> (64,)
    final_kernel<<<NB, 128>>>(w5, b5, out);
}

// round 5
// speedup vs baseline: 1.1671x; 1.1671x over previous
#include <cuda_runtime.h>
#include <cstdint>

// ===========================================================================
// WireframeDiscriminator: render -> conv1..3 (5x5 s2 + BN(batch) + LReLU)
//                         -> conv4 (8x8 dense == GEMM) + BN + LReLU -> conv5
// fp32 math via packed fma.rn.f32x2 (FFMA2, 2 FMAs/issue on sm_103a).
// ===========================================================================

#define NB 64   // batch

typedef unsigned long long u64;

__device__ __forceinline__ u64 fma2(u64 a, u64 b, u64 c){
    u64 d;
    asm("fma.rn.f32x2 %0, %1, %2, %3;" : "=l"(d) : "l"(a), "l"(b), "l"(c));
    return d;
}
__device__ __forceinline__ u64 pack2(float x, float y){
    u64 d;
    asm("mov.b64 %0, {%1, %2};" : "=l"(d) : "f"(x), "f"(y));
    return d;
}
__device__ __forceinline__ float2 unpack2(u64 v){
    float2 r;
    asm("mov.b64 {%0, %1}, %2;" : "=f"(r.x), "=f"(r.y) : "l"(v));
    return r;
}

// ---------------- scratch ----------------
__device__ __align__(16) float g_rend[NB*14*64*64];    // 14.7 MB
__device__ __align__(16) float g_h1[NB*64*32*32];      // 16.8 MB
__device__ __align__(16) float g_h2[NB*128*16*16];     //  8.4 MB
__device__ __align__(16) float g_h3[NB*256*8*8];       //  4.2 MB
__device__ __align__(16) float g_h4[NB*1024];
__device__ __align__(16) float g_h4p[16*NB*1024];      // split-K partials
__device__ __align__(16) float g_w1t[14*25*64];
__device__ __align__(16) float g_w2t[64*25*128];
__device__ __align__(16) float g_w3t[128*25*256];
__device__ float g_scale[1024];
__device__ float g_shift[1024];

// ---------------- weight transpose: [oc][ic][kh][kw] -> [ic][kh][kw][oc] ----
template<int OC,int IC,int KS>
__global__ void wtrans_kernel(const float* __restrict__ w, float* __restrict__ wt){
    int n = OC*IC*KS*KS;
    int i = blockIdx.x*blockDim.x + threadIdx.x;
    if (i >= n) return;
    int kw = i % KS; int t = i / KS;
    int kh = t % KS; t /= KS;
    int ic = t % IC; int oc = t / IC;
    wt[((ic*KS + kh)*KS + kw)*OC + oc] = w[i];
}

// ---------------- render: elements (B,46,18) -> g_rend (B,14,64,64) --------
__global__ void render_kernel(const float* __restrict__ elems){
    __shared__ float s_cls[46][14];
    __shared__ float s_rect[46][4];
    __shared__ float s_geo[46][4];   // x0,x1,y0,y1
    int b   = blockIdx.x >> 4;
    int pix = ((blockIdx.x & 15) << 8) + threadIdx.x;   // 0..4095
    const float* eb = elems + b*46*18;
    for (int i = threadIdx.x; i < 46*18; i += 256){
        int n = i/18, c = i%18;
        float v = eb[i];
        if (c < 14) s_cls[n][c] = v; else s_rect[n][c-14] = v;
    }
    __syncthreads();
    if (threadIdx.x < 46){
        int n = threadIdx.x;
        float x = s_rect[n][0]*64.f, y = s_rect[n][1]*64.f;
        float w = s_rect[n][2]*64.f, h = s_rect[n][3]*64.f;
        s_geo[n][0] = x - 0.5f*w;
        s_geo[n][1] = x + 0.5f*w;
        s_geo[n][2] = y - 0.5f*h;
        s_geo[n][3] = y + 0.5f*h;
    }
    __syncthreads();

    float cy = (float)(pix >> 6);
    float cx = (float)(pix & 63);
    float acc[14];
    #pragma unroll
    for (int c = 0; c < 14; c++) acc[c] = 0.f;

    for (int n = 0; n < 46; n++){
        float x0 = s_geo[n][0], x1 = s_geo[n][1];
        float y0 = s_geo[n][2], y1 = s_geo[n][3];
        float by = __saturatef(cy - y0) * __saturatef(y1 - cy);
        float bx = __saturatef(cx - x0) * __saturatef(x1 - cx);
        float l0 = fmaxf(1.f - fabsf(cx - x0), 0.f) * by;
        float l1 = fmaxf(1.f - fabsf(cx - x1), 0.f) * by;
        float l2 = fmaxf(1.f - fabsf(cy - y0), 0.f) * bx;
        float l3 = fmaxf(1.f - fabsf(cy - y1), 0.f) * bx;
        float r  = fmaxf(fmaxf(l0, l1), fmaxf(l2, l3));
        if (r > 0.f){
            #pragma unroll
            for (int c = 0; c < 14; c++) acc[c] = fmaf(s_cls[n][c], r, acc[c]);
        }
    }
    float* ob = g_rend + (size_t)b*14*4096 + pix;
    #pragma unroll
    for (int c = 0; c < 14; c++) ob[c*4096] = acc[c];
}

// ---------------- direct 5x5 stride-2 pad-2 conv, 4oc x 4ow register tile --
// FFMA2 version: accumulators paired along oc; weight float4 = 2 packed ops.
// weights pre-transposed to [ic][kh][kw][oc]; block = (b, oh); 128 threads.
template<int IC,int IH,int IW,int OC,int OH,int OW>
__global__ void __launch_bounds__(128)
conv5s2_kernel(const float* __restrict__ in, const float* __restrict__ wt,
               float* __restrict__ out){
    constexpr int KS = 5, ST = 2, PD = 2, OCT = 4, OWT = 4;
    constexpr int NOWT = OW/OWT;
    constexpr int SPAN = (OWT-1)*ST + KS;   // 11
    int tid   = threadIdx.x;
    int owt   = tid % NOWT;
    int oct   = tid / NOWT;
    int b     = blockIdx.x / OH;
    int oh    = blockIdx.x % OH;
    int ow0   = owt*OWT;
    int xbase = ow0*ST - PD;
    int ybase = oh*ST - PD;

    u64 acc[OWT][2];
    #pragma unroll
    for (int i = 0; i < OWT; i++){ acc[i][0] = 0ull; acc[i][1] = 0ull; }

    const float* ip0 = in + (size_t)b*IC*IH*IW;
    #pragma unroll 1
    for (int ic = 0; ic < IC; ++ic){
        const float* ip = ip0 + ic*IH*IW;
        const float* wp = wt + ic*KS*KS*OC + oct*OCT;
        #pragma unroll
        for (int kh = 0; kh < KS; ++kh){
            int y = ybase + kh;
            u64 vp[SPAN];
            if ((unsigned)y < (unsigned)IH){
                const float* row = ip + y*IW;
                #pragma unroll
                for (int s = 0; s < SPAN; s++){
                    int x = xbase + s;
                    float v = ((unsigned)x < (unsigned)IW) ? __ldg(row + x) : 0.f;
                    vp[s] = pack2(v, v);
                }
            } else {
                #pragma unroll
                for (int s = 0; s < SPAN; s++) vp[s] = 0ull;
            }
            #pragma unroll
            for (int kw = 0; kw < KS; ++kw){
                ulonglong2 wq = *reinterpret_cast<const ulonglong2*>(wp + (kh*KS + kw)*OC);
                #pragma unroll
                for (int i = 0; i < OWT; i++){
                    u64 xv = vp[kw + i*ST];
                    acc[i][0] = fma2(xv, wq.x, acc[i][0]);
                    acc[i][1] = fma2(xv, wq.y, acc[i][1]);
                }
            }
        }
    }
    float r[OWT][4];
    #pragma unroll
    for (int i = 0; i < OWT; i++){
        float2 p0 = unpack2(acc[i][0]);
        float2 p1 = unpack2(acc[i][1]);
        r[i][0] = p0.x; r[i][1] = p0.y; r[i][2] = p1.x; r[i][3] = p1.y;
    }
    #pragma unroll
    for (int j = 0; j < OCT; j++){
        float* op = out + (((size_t)b*OC + oct*OCT + j)*OH + oh)*OW + ow0;
        #pragma unroll
        for (int i = 0; i < OWT; i++) op[i] = r[i][j];
    }
}

// ---------------- BN (batch statistics over N,H,W) --------------------------
// fp32 per-thread accumulation (<=1024 vals/thread), double tree reduce.
template<int C,int HW>
__global__ void bn_stats_kernel(const float* __restrict__ x,
                                const float* __restrict__ gamma,
                                const float* __restrict__ beta){
    int c = blockIdx.x;
    constexpr int Q = HW/4;
    float s = 0.f, ss = 0.f;
    for (int idx = threadIdx.x; idx < NB*Q; idx += blockDim.x){
        int b = idx / Q, i = idx % Q;
        float4 v = reinterpret_cast<const float4*>(x + ((size_t)b*C + c)*HW)[i];
        s  += (v.x + v.y) + (v.z + v.w);
        ss  = fmaf(v.x, v.x, ss); ss = fmaf(v.y, v.y, ss);
        ss  = fmaf(v.z, v.z, ss); ss = fmaf(v.w, v.w, ss);
    }
    __shared__ double sh_s[256], sh_ss[256];
    int tid = threadIdx.x;
    sh_s[tid] = (double)s; sh_ss[tid] = (double)ss;
    __syncthreads();
    for (int st = 128; st > 0; st >>= 1){
        if (tid < st){ sh_s[tid] += sh_s[tid+st]; sh_ss[tid] += sh_ss[tid+st]; }
        __syncthreads();
    }
    if (tid == 0){
        double n   = (double)NB * (double)HW;
        double m   = sh_s[0] / n;
        double var = sh_ss[0] / n - m*m;
        float rstd = (float)rsqrt(var + 1e-5);
        float g    = gamma[c];
        g_scale[c] = g * rstd;
        g_shift[c] = beta[c] - (float)m * g * rstd;
    }
}

template<int C,int HW>
__global__ void bn_apply_kernel(float* __restrict__ x){
    int i = blockIdx.x*blockDim.x + threadIdx.x;       // over total/4
    int c = (i / (HW/4)) % C;
    float sc = g_scale[c], sh = g_shift[c];
    float4 v = reinterpret_cast<float4*>(x)[i];
    v.x = fmaf(v.x, sc, sh); v.x = (v.x >= 0.f) ? v.x : 0.01f*v.x;
    v.y = fmaf(v.y, sc, sh); v.y = (v.y >= 0.f) ? v.y : 0.01f*v.y;
    v.z = fmaf(v.z, sc, sh); v.z = (v.z >= 0.f) ? v.z : 0.01f*v.z;
    v.w = fmaf(v.w, sc, sh); v.w = (v.w >= 0.f) ? v.w : 0.01f*v.w;
    reinterpret_cast<float4*>(x)[i] = v;
}

// ---------------- conv4 as split-K GEMM: [64 x 16384] x [16384 x 1024] -----
// grid = 16 oc-blocks * 16 K-splits; block tile 64b x 64oc; thread 4x4 (FFMA2).
__global__ void __launch_bounds__(256)
gemm_kernel(const float* __restrict__ W4){
    constexpr int KC = 16;
    constexpr int KSPLIT = 16;
    constexpr int KLEN = 16384 / KSPLIT;   // 1024
    int ocb = blockIdx.x / KSPLIT;
    int ks  = blockIdx.x % KSPLIT;
    int tid = threadIdx.x;
    int tx  = tid & 15;        // -> 4 oc
    int ty  = tid >> 4;        // -> 4 b
    __shared__ __align__(16) float As[KC][68];
    __shared__ __align__(16) float Ws[KC][68];

    u64 acc[4][2];
    #pragma unroll
    for (int i = 0; i < 4; i++){ acc[i][0] = 0ull; acc[i][1] = 0ull; }

    const float* A  = g_h3;
    const float* Wb = W4 + (size_t)ocb*64*16384;
    int k0 = ks*KLEN;

    for (int kc = 0; kc < KLEN; kc += KC){
        #pragma unroll
        for (int l = 0; l < 4; l++){
            int idx = tid + l*256;
            int r = idx >> 4, kk = idx & 15;
            As[kk][r] = A [(size_t)r*16384 + k0 + kc + kk];
            Ws[kk][r] = Wb[(size_t)r*16384 + k0 + kc + kk];
        }
        __syncthreads();
        #pragma unroll
        for (int kk = 0; kk < KC; kk++){
            float4 a = *reinterpret_cast<const float4*>(&As[kk][ty*4]);
            ulonglong2 w2 = *reinterpret_cast<const ulonglong2*>(&Ws[kk][tx*4]);
            u64 a0 = pack2(a.x, a.x), a1 = pack2(a.y, a.y);
            u64 a2 = pack2(a.z, a.z), a3 = pack2(a.w, a.w);
            acc[0][0] = fma2(a0, w2.x, acc[0][0]); acc[0][1] = fma2(a0, w2.y, acc[0][1]);
            acc[1][0] = fma2(a1, w2.x, acc[1][0]); acc[1][1] = fma2(a1, w2.y, acc[1][1]);
            acc[2][0] = fma2(a2, w2.x, acc[2][0]); acc[2][1] = fma2(a2, w2.y, acc[2][1]);
            acc[3][0] = fma2(a3, w2.x, acc[3][0]); acc[3][1] = fma2(a3, w2.y, acc[3][1]);
        }
        __syncthreads();
    }
    float* op = g_h4p + (size_t)ks*NB*1024;
    #pragma unroll
    for (int i = 0; i < 4; i++){
        float2 p0 = unpack2(acc[i][0]);
        float2 p1 = unpack2(acc[i][1]);
        float* q = op + (ty*4 + i)*1024 + ocb*64 + tx*4;
        q[0] = p0.x; q[1] = p0.y; q[2] = p1.x; q[3] = p1.y;
    }
}

// deterministic split-K reduction (float4)
__global__ void ksum_kernel(){
    int i = blockIdx.x*blockDim.x + threadIdx.x;   // over 16384 float4s
    float4 s = make_float4(0.f, 0.f, 0.f, 0.f);
    #pragma unroll
    for (int k = 0; k < 16; k++){
        float4 v = reinterpret_cast<const float4*>(g_h4p + (size_t)k*NB*1024)[i];
        s.x += v.x; s.y += v.y; s.z += v.z; s.w += v.w;
    }
    reinterpret_cast<float4*>(g_h4)[i] = s;
}

// ---------------- BN4 (per channel over 64 batch values) -------------------
__global__ void bn4_stats_kernel(const float* __restrict__ gamma,
                                 const float* __restrict__ beta){
    int c = blockIdx.x*blockDim.x + threadIdx.x;   // 1024 threads
    float s = 0.f, ss = 0.f;
    for (int b = 0; b < NB; b++){
        float v = g_h4[b*1024 + c];
        s += v; ss = fmaf(v, v, ss);
    }
    float m    = s * (1.f/NB);
    float var  = ss * (1.f/NB) - m*m;
    float rstd = rsqrtf(var + 1e-5f);
    float g    = gamma[c];
    g_scale[c] = g * rstd;
    g_shift[c] = beta[c] - m * g * rstd;
}

// ---------------- final: lrelu(bn4(h4)) . w5 + b5 --------------------------
__global__ void final_kernel(const float* __restrict__ w5,
                             const float* __restrict__ b5,
                             float* __restrict__ out){
    int b = blockIdx.x, tid = threadIdx.x;
    float p = 0.f;
    for (int c = tid; c < 1024; c += 128){
        float v = fmaf(g_h4[b*1024 + c], g_scale[c], g_shift[c]);
        v = (v >= 0.f) ? v : 0.01f*v;
        p = fmaf(w5[c], v, p);
    }
    __shared__ float red[128];
    red[tid] = p;
    __syncthreads();
    for (int st = 64; st > 0; st >>= 1){
        if (tid < st) red[tid] += red[tid + st];
        __syncthreads();
    }
    if (tid == 0) out[b] = red[0] + b5[0];
}

// ===========================================================================
extern "C" void kernel_launch(void* const* d_in, const int* in_sizes, int n_in,
                              void* d_out, int out_size){
    const float* input_data = (const float*)d_in[0];
    // d_in[1] = input_length (unused by reference)
    const float* w1 = (const float*)d_in[2];
    const float* g1 = (const float*)d_in[3];
    const float* b1 = (const float*)d_in[4];
    const float* w2 = (const float*)d_in[5];
    const float* g2 = (const float*)d_in[6];
    const float* b2 = (const float*)d_in[7];
    const float* w3 = (const float*)d_in[8];
    const float* g3 = (const float*)d_in[9];
    const float* b3 = (const float*)d_in[10];
    const float* w4 = (const float*)d_in[11];
    const float* g4 = (const float*)d_in[12];
    const float* b4 = (const float*)d_in[13];
    const float* w5 = (const float*)d_in[14];
    const float* b5 = (const float*)d_in[15];
    float* out = (float*)d_out;

    float *p_rend, *p_h1, *p_h2, *p_h3, *p_w1t, *p_w2t, *p_w3t;
    cudaGetSymbolAddress((void**)&p_rend, g_rend);
    cudaGetSymbolAddress((void**)&p_h1,   g_h1);
    cudaGetSymbolAddress((void**)&p_h2,   g_h2);
    cudaGetSymbolAddress((void**)&p_h3,   g_h3);
    cudaGetSymbolAddress((void**)&p_w1t,  g_w1t);
    cudaGetSymbolAddress((void**)&p_w2t,  g_w2t);
    cudaGetSymbolAddress((void**)&p_w3t,  g_w3t);

    // weight transposes (tiny)
    wtrans_kernel<64,14,5>  <<<(64*14*25   + 255)/256, 256>>>(w1, p_w1t);
    wtrans_kernel<128,64,5> <<<(128*64*25  + 255)/256, 256>>>(w2, p_w2t);
    wtrans_kernel<256,128,5><<<(256*128*25 + 255)/256, 256>>>(w3, p_w3t);

    // render
    render_kernel<<<NB*16, 256>>>(input_data);

    // conv1 + BN + LReLU
    conv5s2_kernel<14,64,64, 64,32,32><<<NB*32, 128>>>(p_rend, p_w1t, p_h1);
    bn_stats_kernel<64,1024><<<64, 256>>>(p_h1, g1, b1);
    bn_apply_kernel<64,1024><<<(NB*64*1024/4)/256, 256>>>(p_h1);

    // conv2 + BN + LReLU
    conv5s2_kernel<64,32,32, 128,16,16><<<NB*16, 128>>>(p_h1, p_w2t, p_h2);
    bn_stats_kernel<128,256><<<128, 256>>>(p_h2, g2, b2);
    bn_apply_kernel<128,256><<<(NB*128*256/4)/256, 256>>>(p_h2);

    // conv3 + BN + LReLU
    conv5s2_kernel<128,16,16, 256,8,8><<<NB*8, 128>>>(p_h2, p_w3t, p_h3);
    bn_stats_kernel<256,64><<<256, 256>>>(p_h3, g3, b3);
    bn_apply_kernel<256,64><<<(NB*256*64/4)/256, 256>>>(p_h3);

    // conv4 (split-K GEMM, deterministic reduce) + BN4
    gemm_kernel<<<16*16, 256>>>(w4);
    ksum_kernel<<<(NB*1024/4)/256, 256>>>();
    bn4_stats_kernel<<<4, 256>>>(g4, b4);

    // conv5 + bias -> (64,)
    final_kernel<<<NB, 128>>>(w5, b5, out);
}